// round 3
// baseline (speedup 1.0000x reference)
#include <cuda_runtime.h>
#include <cuda_bf16.h>
#include <stdint.h>

// ---------------- problem dims ----------------
#define BATCH 8
#define CIN   2
#define HH    64
#define WW    64
#define TT    200
#define NCH   7      // ceil(200/32) chunks of 32 timesteps (internal T=224, tail garbage is causal-safe)
#define C1    8
#define C2    8

// fp32 correctly-rounded decay constants
#define D1 0.36787944117144233f   // exp(-1)    : tau=1 (psp1, ref1)
#define D2 0.60653065971263342f   // exp(-1/2)  : tau=2 (psp2, ref2)
#define D3 0.77880078307140487f   // exp(-1/4)  : tau=4 (psp3, ref3)

// ---------------- bit-packed intermediates ----------------
// layout: [b][chunk][c][h][w], one uint32 = 32 consecutive timesteps
__device__ uint32_t g_xbits[BATCH * NCH * CIN * HH * WW];  // 1.75 MB
__device__ uint32_t g_s1  [BATCH * NCH * C1  * HH * WW];   // 7 MB
__device__ uint32_t g_s2  [BATCH * NCH * C2  * HH * WW];   // 7 MB

// =====================================================================
// K0: binarize + time-transpose input [b,c,h,w,t] -> bitmasks
// =====================================================================
__global__ void k_binarize(const float* __restrict__ x) {
    int tid = blockIdx.x * blockDim.x + threadIdx.x;
    if (tid >= BATCH * CIN * HH * WW * NCH) return;
    int k   = tid % NCH;
    int pix = tid / NCH;                  // (b*CIN+c)*HH*WW + h*WW + w
    int w = pix % WW; int t1 = pix / WW;
    int h = t1 % HH;  t1 /= HH;
    int c = t1 % CIN; int b = t1 / CIN;
    const float* p = x + (size_t)pix * TT + k * 32;
    int n = min(32, TT - k * 32);
    uint32_t bits = 0;
    for (int i = 0; i < n; i++) bits |= (p[i] > 0.5f) ? (1u << i) : 0u;
    g_xbits[(((b * NCH + k) * CIN + c) * HH + h) * WW + w] = bits;
}

// =====================================================================
// K1: layer 1.  u = IIR_1(conv5x5(xbits)); spike(th=30, dref=D1)
// one thread = (b,h,w), all 8 out-channels, all 200 timesteps
// =====================================================================
__global__ void __launch_bounds__(128) k_layer1(const float* __restrict__ w1) {
    __shared__ float sw[C1 * CIN * 25];
    for (int i = threadIdx.x; i < C1 * CIN * 25; i += blockDim.x) sw[i] = w1[i];
    __syncthreads();

    int tid = blockIdx.x * blockDim.x + threadIdx.x;
    int w = tid % WW; int t1 = tid / WW;
    int h = t1 % HH;  int b = t1 / HH;

    float a[C1], r[C1];
#pragma unroll
    for (int o = 0; o < C1; o++) { a[o] = 0.f; r[o] = 0.f; }

    for (int k = 0; k < NCH; k++) {
        uint32_t bits[CIN * 25];
#pragma unroll
        for (int c = 0; c < CIN; c++)
#pragma unroll
            for (int dy = 0; dy < 5; dy++)
#pragma unroll
                for (int dx = 0; dx < 5; dx++) {
                    int hh = h + dy - 2, ww = w + dx - 2;
                    uint32_t v = 0;
                    if (hh >= 0 && hh < HH && ww >= 0 && ww < WW)
                        v = g_xbits[(((b * NCH + k) * CIN + c) * HH + hh) * WW + ww];
                    bits[(c * 5 + dy) * 5 + dx] = v;
                }
#pragma unroll 1
        for (int o = 0; o < C1; o++) {
            float sums[32];
#pragma unroll
            for (int j = 0; j < 32; j++) sums[j] = 0.f;
#pragma unroll
            for (int tp = 0; tp < CIN * 25; tp++) {
                float wv = sw[o * CIN * 25 + tp];
                uint32_t bw = bits[tp];
#pragma unroll
                for (int j = 0; j < 32; j++)
                    if (bw & (1u << j)) sums[j] += wv;
            }
            uint32_t sb = 0;
            float av = a[o], rv = r[o];
#pragma unroll
            for (int j = 0; j < 32; j++) {
                av = D1 * av + sums[j];
                float v = av + rv;
                bool hd = v >= 30.0f;
                sb |= hd ? (1u << j) : 0u;
                rv = D1 * rv - (hd ? 30.0f : 0.0f);
            }
            a[o] = av; r[o] = rv;
            g_s1[(((b * NCH + k) * C1 + o) * HH + h) * WW + w] = sb;
        }
    }
}

// =====================================================================
// K2: layer 2.  u = IIR_2(conv3x3(s1bits)); spike(th=50, dref=D2)
// =====================================================================
__global__ void __launch_bounds__(128) k_layer2(const float* __restrict__ w2) {
    __shared__ float sw[C2 * C1 * 9];
    for (int i = threadIdx.x; i < C2 * C1 * 9; i += blockDim.x) sw[i] = w2[i];
    __syncthreads();

    int tid = blockIdx.x * blockDim.x + threadIdx.x;
    int w = tid % WW; int t1 = tid / WW;
    int h = t1 % HH;  int b = t1 / HH;

    float a[C2], r[C2];
#pragma unroll
    for (int o = 0; o < C2; o++) { a[o] = 0.f; r[o] = 0.f; }

    for (int k = 0; k < NCH; k++) {
        uint32_t bits[C1 * 9];
#pragma unroll
        for (int c = 0; c < C1; c++)
#pragma unroll
            for (int dy = 0; dy < 3; dy++)
#pragma unroll
                for (int dx = 0; dx < 3; dx++) {
                    int hh = h + dy - 1, ww = w + dx - 1;
                    uint32_t v = 0;
                    if (hh >= 0 && hh < HH && ww >= 0 && ww < WW)
                        v = g_s1[(((b * NCH + k) * C1 + c) * HH + hh) * WW + ww];
                    bits[(c * 3 + dy) * 3 + dx] = v;
                }
#pragma unroll 1
        for (int o = 0; o < C2; o++) {
            float sums[32];
#pragma unroll
            for (int j = 0; j < 32; j++) sums[j] = 0.f;
#pragma unroll
            for (int tp = 0; tp < C1 * 9; tp++) {
                float wv = sw[o * C1 * 9 + tp];
                uint32_t bw = bits[tp];
#pragma unroll
                for (int j = 0; j < 32; j++)
                    if (bw & (1u << j)) sums[j] += wv;
            }
            uint32_t sb = 0;
            float av = a[o], rv = r[o];
#pragma unroll
            for (int j = 0; j < 32; j++) {
                av = D2 * av + sums[j];
                float v = av + rv;
                bool hd = v >= 50.0f;
                sb |= hd ? (1u << j) : 0u;
                rv = D2 * rv - (hd ? 50.0f : 0.0f);
            }
            a[o] = av; r[o] = rv;
            g_s2[(((b * NCH + k) * C2 + o) * HH + h) * WW + w] = sb;
        }
    }
}

// =====================================================================
// K3: layer 3.
//   u3 = IIR_4(convT2x2(s2bits)) + IIR_1(bilinear2x(xbits)); spike(th=100, dref=D3)
//   convT k=2 s=2 VALID: out[o, 2h+a, 2w+bb] += s2[c,h,w] * wup[o,c,1-a,1-bb]
//   bilinear half-pixel taps: even idx -> (i-1:0.25, i:0.75), odd -> (i:0.75, i+1:0.25)
//   (jax renormalizes truncated edge kernels == edge clamp for 2-tap triangle)
//   Output written dense float32 [8,2,128,128,200] via warp shfl-transpose (coalesced t-runs).
// =====================================================================
__global__ void __launch_bounds__(128) k_layer3(const float* __restrict__ wup,
                                                float* __restrict__ out) {
    __shared__ float swu[64];                       // 2*8*2*2 = 64 weights (was the OOB bug)
    if (threadIdx.x < 64) swu[threadIdx.x] = wup[threadIdx.x];
    __syncthreads();

    int tid = blockIdx.x * blockDim.x + threadIdx.x;
    int wo = tid & 127; int t1 = tid >> 7;
    int ho = t1 & 127;  int b  = t1 >> 7;
    int hi = ho >> 1, wi = wo >> 1;
    int pa = ho & 1,  pb = wo & 1;

    int r0, r1, c0, c1; float wr0, wr1, wc0, wc1;
    if (!pa) { r0 = (hi > 0) ? hi - 1 : 0;  r1 = hi; wr0 = 0.25f; wr1 = 0.75f; }
    else     { r0 = hi; r1 = (hi < 63) ? hi + 1 : 63; wr0 = 0.75f; wr1 = 0.25f; }
    if (!pb) { c0 = (wi > 0) ? wi - 1 : 0;  c1 = wi; wc0 = 0.25f; wc1 = 0.75f; }
    else     { c0 = wi; c1 = (wi < 63) ? wi + 1 : 63; wc0 = 0.75f; wc1 = 0.25f; }
    float tw00 = wr0 * wc0, tw01 = wr0 * wc1, tw10 = wr1 * wc0, tw11 = wr1 * wc1;

    int lane = threadIdx.x & 31;
    int wo0  = wo & ~31;   // lane 0's wo (warp = 32 consecutive wo, same b,ho)

    float a[2], p[2], rr[2];
#pragma unroll
    for (int o = 0; o < 2; o++) { a[o] = 0.f; p[o] = 0.f; rr[o] = 0.f; }

    for (int k = 0; k < NCH; k++) {
        uint32_t s2b[C2];
#pragma unroll
        for (int c = 0; c < C2; c++)
            s2b[c] = g_s2[(((b * NCH + k) * C2 + c) * HH + hi) * WW + wi];
        uint32_t xb00[2], xb01[2], xb10[2], xb11[2];
#pragma unroll
        for (int c = 0; c < 2; c++) {
            const uint32_t* xp = g_xbits + (size_t)(((b * NCH + k) * CIN) + c) * HH * WW;
            xb00[c] = xp[r0 * WW + c0]; xb01[c] = xp[r0 * WW + c1];
            xb10[c] = xp[r1 * WW + c0]; xb11[c] = xp[r1 * WW + c1];
        }
#pragma unroll 1
        for (int o = 0; o < 2; o++) {
            float sA[32], sX[32];
#pragma unroll
            for (int j = 0; j < 32; j++) { sA[j] = 0.f; sX[j] = 0.f; }
#pragma unroll
            for (int c = 0; c < C2; c++) {
                float wv = swu[((o * 8 + c) * 2 + (1 - pa)) * 2 + (1 - pb)];
                uint32_t bw = s2b[c];
#pragma unroll
                for (int j = 0; j < 32; j++)
                    if (bw & (1u << j)) sA[j] += wv;
            }
            {
                uint32_t bw = xb00[o];
#pragma unroll
                for (int j = 0; j < 32; j++) if (bw & (1u << j)) sX[j] += tw00;
            }
            {
                uint32_t bw = xb01[o];
#pragma unroll
                for (int j = 0; j < 32; j++) if (bw & (1u << j)) sX[j] += tw01;
            }
            {
                uint32_t bw = xb10[o];
#pragma unroll
                for (int j = 0; j < 32; j++) if (bw & (1u << j)) sX[j] += tw10;
            }
            {
                uint32_t bw = xb11[o];
#pragma unroll
                for (int j = 0; j < 32; j++) if (bw & (1u << j)) sX[j] += tw11;
            }
            uint32_t sb = 0;
            float av = a[o], pv = p[o], rv = rr[o];
#pragma unroll
            for (int j = 0; j < 32; j++) {
                av = D3 * av + sA[j];
                pv = D1 * pv + sX[j];
                float v = av + pv + rv;
                bool hd = v >= 100.0f;
                sb |= hd ? (1u << j) : 0u;
                rv = D3 * rv - (hd ? 100.0f : 0.0f);
            }
            a[o] = av; p[o] = pv; rr[o] = rv;

            // transposed coalesced store: lane writes t = 32k+lane of pixel (wo0+pl)
            size_t rowbase = ((size_t)((b * 2 + o) * 128 + ho) * 128 + wo0) * TT;
            int t = k * 32 + lane;
#pragma unroll
            for (int pl = 0; pl < 32; pl++) {
                uint32_t wv = __shfl_sync(0xffffffffu, sb, pl);
                if (t < TT)
                    out[rowbase + (size_t)pl * TT + t] = ((wv >> lane) & 1u) ? 1.0f : 0.0f;
            }
        }
    }
}

// =====================================================================
extern "C" void kernel_launch(void* const* d_in, const int* in_sizes, int n_in,
                              void* d_out, int out_size) {
    const float* x   = (const float*)d_in[0];
    const float* w1  = (const float*)d_in[1];
    const float* w2  = (const float*)d_in[2];
    const float* wup = (const float*)d_in[3];
    float* out = (float*)d_out;

    int n0 = BATCH * CIN * HH * WW * NCH;           // 458752
    k_binarize<<<(n0 + 255) / 256, 256>>>(x);
    k_layer1<<<(BATCH * HH * WW) / 128, 128>>>(w1);     // 256 blocks
    k_layer2<<<(BATCH * HH * WW) / 128, 128>>>(w2);     // 256 blocks
    k_layer3<<<(BATCH * 128 * 128) / 128, 128>>>(wup, out); // 1024 blocks
}